// round 9
// baseline (speedup 1.0000x reference)
#include <cuda_runtime.h>
#include <cuda_fp16.h>
#include <math.h>

#define Bz   4
#define Nn   8192
#define Cc   32
#define Kk   16
#define Hh   64
#define OUTC 128
#define CE   36
#define S_TOT (Bz*Nn*Kk)        // 524288
#define P_TOT (Bz*Nn)           // 32768
#define INV_S (1.f/524288.f)
#define INV_P (1.f/32768.f)

// ---------------- scratch -----------------------------------------------------
__device__ __half g_y1 [S_TOT*Hh];
__device__ __half g_y2 [S_TOT*Hh];
__device__ float  g_g1 [P_TOT*Hh];
__device__ float  g_g2 [P_TOT*Hh];
__device__ float  g_agg[P_TOT*OUTC];
__device__ float  g_h1 [P_TOT*OUTC];
__device__ float  g_h2 [P_TOT*OUTC];
__device__ int    g_idx[S_TOT];
__device__ float  d_stats[8*256];

__device__ __forceinline__ unsigned tf32r(float f) {
    unsigned r; asm("cvt.rna.tf32.f32 %0, %1;" : "=r"(r) : "f"(f)); return r;
}
#define MMA_TF32(d, a, b) asm volatile( \
    "mma.sync.aligned.m16n8k8.row.col.f32.tf32.tf32.f32 " \
    "{%0,%1,%2,%3}, {%4,%5,%6,%7}, {%8,%9}, {%0,%1,%2,%3};" \
    : "+f"(d[0]),"+f"(d[1]),"+f"(d[2]),"+f"(d[3]) \
    : "r"(a[0]),"r"(a[1]),"r"(a[2]),"r"(a[3]), "r"(b[0]),"r"(b[1]))
#define MMA_F16(d, a, b) asm volatile( \
    "mma.sync.aligned.m16n8k16.row.col.f32.f16.f16.f32 " \
    "{%0,%1,%2,%3}, {%4,%5,%6,%7}, {%8,%9}, {%0,%1,%2,%3};" \
    : "+f"(d[0]),"+f"(d[1]),"+f"(d[2]),"+f"(d[3]) \
    : "r"(a[0]),"r"(a[1]),"r"(a[2]),"r"(a[3]), "r"(b[0]),"r"(b[1]))

__device__ __forceinline__ unsigned pack_h2(float a, float b) {
    __half2 h = __floats2half2_rn(a, b);
    return *(unsigned*)&h;
}
__device__ __forceinline__ void split_h2(float a, float b, unsigned &hi, unsigned &lo) {
    __half ha = __float2half_rn(a), hb = __float2half_rn(b);
    float la = a - __half2float(ha), lb = b - __half2float(hb);
    __half2 h = __halves2half2(ha, hb);
    __half2 l = __floats2half2_rn(la, lb);
    hi = *(unsigned*)&h; lo = *(unsigned*)&l;
}

__global__ void zero_stats_kernel() {
    int t = blockIdx.x*256 + threadIdx.x;
    if (t < 8*256) d_stats[t] = 0.f;
}

// ---------------- KNN ---------------------------------------------------------
#define KNN_T    128
#define KNN_TILE 1024
__global__ void knn_kernel(const float* __restrict__ xyz) {
    int b = blockIdx.y;
    int n = blockIdx.x*KNN_T + threadIdx.x;
    const float* xb = xyz + b*Nn*3;
    float qx = xb[n*3+0], qy = xb[n*3+1], qz = xb[n*3+2];
    float m2x = -2.f*qx, m2y = -2.f*qy, m2z = -2.f*qz;
    float bd[16]; int bi[16];
#pragma unroll
    for (int t=0;t<16;t++){ bd[t]=3.4e38f; bi[t]=0; }
    __shared__ float4 sp[KNN_TILE];
    for (int tile=0; tile<Nn; tile+=KNN_TILE) {
        __syncthreads();
        for (int t=threadIdx.x; t<KNN_TILE; t+=KNN_T) {
            int j = tile + t;
            float x = xb[j*3+0], y = xb[j*3+1], z = xb[j*3+2];
            float w = x*x; w = fmaf(y,y,w); w = fmaf(z,z,w);
            sp[t] = make_float4(x, y, z, w);
        }
        __syncthreads();
#pragma unroll 8
        for (int jj=0; jj<KNN_TILE; jj++) {
            float4 c = sp[jj];
            float d = fmaf(c.x, m2x, fmaf(c.y, m2y, fmaf(c.z, m2z, c.w)));
            if (d < bd[15]) {
                bd[15]=d; bi[15]=tile+jj;
#pragma unroll
                for (int t=15;t>0;t--) {
                    if (bd[t] < bd[t-1]) {
                        float td=bd[t]; bd[t]=bd[t-1]; bd[t-1]=td;
                        int   ti=bi[t]; bi[t]=bi[t-1]; bi[t-1]=ti;
                    }
                }
            }
        }
    }
    int base = (b*Nn + n)*Kk;
#pragma unroll
    for (int t=0;t<16;t++) g_idx[base+t] = bi[t];
}

// ---------------- LSE (3xFP16 split, pipelined gather) ------------------------
#define LSE_TILES 16
__global__ void lse_mma_kernel(const float* __restrict__ xyz, const float* __restrict__ feat,
                               const float* __restrict__ w1, const float* __restrict__ w2,
                               __half* __restrict__ y1, __half* __restrict__ y2) {
    __shared__ unsigned encH[64*28], encL[64*28];
    __shared__ unsigned wH[128*28], wL[128*28];
    __shared__ float ssS[128], sqS[128];
    int tid = threadIdx.x;              // 256
    for (int i=tid; i<64*28;  i+=256) { encH[i]=0u; encL[i]=0u; }
    for (int i=tid; i<128*28; i+=256) { wH[i]=0u; wL[i]=0u; }
    if (tid < 128) { ssS[tid]=0.f; sqS[tid]=0.f; }
    __syncthreads();
    for (int i=tid; i<128*18; i+=256) {
        int n = i/18, k2 = i - n*18;
        const float* wsrc = (n < 64) ? (w1 + n*CE) : (w2 + (n-64)*CE);
        unsigned hi, lo;
        split_h2(wsrc[2*k2], wsrc[2*k2+1], hi, lo);
        wH[n*28+k2] = hi; wL[n*28+k2] = lo;
    }
    int w = tid>>5, lane = tid&31, g = lane>>2, t4 = lane&3;
    int wM = w&1, wN = w>>1;
    int sOffW = wM*32, nOffW = wN*32;
    int sl = tid>>2, gq = tid&3;
    float stS[8]={0,0,0,0,0,0,0,0}, stQ[8]={0,0,0,0,0,0,0,0};
    float4 pv0, pv1;
    float aj0=0,aj1=0,aj2=0, an0=0,an1=0,an2=0;
#define LSE_LOAD(T) { \
    int s = (blockIdx.x*LSE_TILES + (T))*64 + sl; \
    int bb = s >> 17; \
    int nn2 = (s >> 4) & (Nn-1); \
    int j = g_idx[s]; \
    const float4* fp = (const float4*)(feat + (size_t)(bb*Nn + j)*Cc + gq*8); \
    pv0 = fp[0]; pv1 = fp[1]; \
    if (gq == 0) { \
        const float* pj = xyz + (size_t)(bb*Nn + j)*3; \
        const float* pn = xyz + (size_t)(bb*Nn + nn2)*3; \
        aj0=pj[0]; aj1=pj[1]; aj2=pj[2]; an0=pn[0]; an1=pn[1]; an2=pn[2]; \
    } }
    LSE_LOAD(0);
    __syncthreads();
    for (int tile=0; tile<LSE_TILES; tile++) {
        int base = (blockIdx.x*LSE_TILES + tile)*64;
        {
            int h0 = sl*28 + 2 + gq*4;
            unsigned hi, lo;
            split_h2(pv0.x, pv0.y, hi, lo); encH[h0  ]=hi; encL[h0  ]=lo;
            split_h2(pv0.z, pv0.w, hi, lo); encH[h0+1]=hi; encL[h0+1]=lo;
            split_h2(pv1.x, pv1.y, hi, lo); encH[h0+2]=hi; encL[h0+2]=lo;
            split_h2(pv1.z, pv1.w, hi, lo); encH[h0+3]=hi; encL[h0+3]=lo;
            if (gq == 0) {
                float dx=aj0-an0, dy=aj1-an1, dz=aj2-an2;
                float dd = dx*dx; dd=fmaf(dy,dy,dd); dd=fmaf(dz,dz,dd);
                float ds = sqrtf(fmaxf(dd,1e-12f));
                split_h2(dx, dy, hi, lo); encH[sl*28  ]=hi; encL[sl*28  ]=lo;
                split_h2(dz, ds, hi, lo); encH[sl*28+1]=hi; encL[sl*28+1]=lo;
            }
        }
        __syncthreads();
        if (tile+1 < LSE_TILES) LSE_LOAD(tile+1);
        float acc[2][4][4];
#pragma unroll
        for (int m=0;m<2;m++)
#pragma unroll
        for (int n=0;n<4;n++)
#pragma unroll
        for (int c=0;c<4;c++) acc[m][n][c]=0.f;
#pragma unroll
        for (int kk=0; kk<3; kk++) {
            int k0 = kk*8;
            unsigned aH[2][4], aL[2][4], bH[4][2], bL[4][2];
#pragma unroll
            for (int m=0;m<2;m++) {
                int r0 = (sOffW + m*16 + g)*28 + k0 + t4;
                aH[m][0]=encH[r0]; aH[m][1]=encH[r0+8*28];
                aH[m][2]=encH[r0+4]; aH[m][3]=encH[r0+8*28+4];
                aL[m][0]=encL[r0]; aL[m][1]=encL[r0+8*28];
                aL[m][2]=encL[r0+4]; aL[m][3]=encL[r0+8*28+4];
            }
#pragma unroll
            for (int n=0;n<4;n++) {
                int rb = (nOffW + n*8 + g)*28 + k0 + t4;
                bH[n][0]=wH[rb]; bH[n][1]=wH[rb+4];
                bL[n][0]=wL[rb]; bL[n][1]=wL[rb+4];
            }
#pragma unroll
            for (int m=0;m<2;m++)
#pragma unroll
            for (int n=0;n<4;n++) {
                MMA_F16(acc[m][n], aL[m], bH[n]);
                MMA_F16(acc[m][n], aH[m], bL[n]);
                MMA_F16(acc[m][n], aH[m], bH[n]);
            }
        }
#pragma unroll
        for (int m=0;m<2;m++)
#pragma unroll
        for (int n=0;n<4;n++) {
            int row = base + sOffW + m*16 + g;
            int col = nOffW + n*8 + 2*t4;
            __half* dst = (col < 64) ? y1 : y2;
            int cc = col & 63;
            __half2 h0 = __floats2half2_rn(acc[m][n][0], acc[m][n][1]);
            __half2 h1 = __floats2half2_rn(acc[m][n][2], acc[m][n][3]);
            *(__half2*)&dst[(size_t)row*Hh + cc]     = h0;
            *(__half2*)&dst[(size_t)(row+8)*Hh + cc] = h1;
            stS[n*2  ] += acc[m][n][0] + acc[m][n][2];
            stS[n*2+1] += acc[m][n][1] + acc[m][n][3];
            stQ[n*2  ] = fmaf(acc[m][n][0],acc[m][n][0], fmaf(acc[m][n][2],acc[m][n][2], stQ[n*2  ]));
            stQ[n*2+1] = fmaf(acc[m][n][1],acc[m][n][1], fmaf(acc[m][n][3],acc[m][n][3], stQ[n*2+1]));
        }
        __syncthreads();
    }
#pragma unroll
    for (int n=0;n<4;n++)
#pragma unroll
    for (int p=0;p<2;p++) {
        int col = nOffW + n*8 + 2*t4 + p;
        atomicAdd(&ssS[col], stS[n*2+p]);
        atomicAdd(&sqS[col], stQ[n*2+p]);
    }
    __syncthreads();
    if (tid < 128) {
        int slot = (tid < 64) ? 0 : 3;
        int ch = tid & 63;
        atomicAdd(&d_stats[slot*256 + ch],      ssS[tid]);
        atomicAdd(&d_stats[slot*256 + 64 + ch], sqS[tid]);
    }
}

// ------- zstats: z = relu(bn(y)) @ sw1^T, stats only (NO z store) -------------
#define XZ_TILES 8
__global__ void zstats_kernel(const __half* __restrict__ y1, const __half* __restrict__ y2,
                              const float* __restrict__ w1b, const float* __restrict__ w2b) {
    int br = blockIdx.y;
    const __half* src = br ? y2 : y1;
    const float*  sw1 = br ? w2b : w1b;
    int slot_y = br ? 3 : 0, slot_z = br ? 4 : 1;
    __shared__ unsigned xH[128*36];
    __shared__ unsigned wHs[64*36];
    __shared__ float mS[64], rS[64], ssS[64], sqS[64];
    int tid = threadIdx.x;              // 256
    for (int i=tid; i<64*32; i+=256) {
        int n = i>>5, k2 = i&31;
        wHs[n*36+k2] = pack_h2(sw1[n*64+2*k2], sw1[n*64+2*k2+1]);
    }
    if (tid < 64) {
        float m = d_stats[slot_y*256+tid]*INV_S;
        float v = d_stats[slot_y*256+64+tid]*INV_S - m*m;
        mS[tid]=m; rS[tid]=rsqrtf(v+1e-5f);
        ssS[tid]=0.f; sqS[tid]=0.f;
    }
    int w = tid>>5, lane = tid&31, g = lane>>2, t4 = lane&3;
    int wM = w&3, wN = w>>2;
    int sOffW = wM*32, nOffW = wN*32;
    float stS[8]={0,0,0,0,0,0,0,0}, stQ[8]={0,0,0,0,0,0,0,0};
    const uint4* sv = (const uint4*)src;
    size_t base0 = (size_t)blockIdx.x*XZ_TILES*128;
    uint4 pf[4];
#pragma unroll
    for (int j=0;j<4;j++) pf[j] = sv[base0*8 + tid*4 + j];
    __syncthreads();
    unsigned bR[4][4][2];
#pragma unroll
    for (int kk=0; kk<4; kk++)
#pragma unroll
    for (int n=0;n<4;n++) {
        int rb = (nOffW + n*8 + g)*36 + kk*8 + t4;
        bR[kk][n][0]=wHs[rb]; bR[kk][n][1]=wHs[rb+4];
    }
    for (int tile=0; tile<XZ_TILES; tile++) {
#pragma unroll
        for (int j=0;j<4;j++) {
            int e = tid*4 + j;
            int s = e>>3, q = e&7, c = q*8;
            __half2* hp = (__half2*)&pf[j];
            float2 f0 = __half22float2(hp[0]);
            float2 f1 = __half22float2(hp[1]);
            float2 f2 = __half22float2(hp[2]);
            float2 f3 = __half22float2(hp[3]);
            uint4 u;
            u.x = pack_h2(fmaxf((f0.x-mS[c  ])*rS[c  ],0.f), fmaxf((f0.y-mS[c+1])*rS[c+1],0.f));
            u.y = pack_h2(fmaxf((f1.x-mS[c+2])*rS[c+2],0.f), fmaxf((f1.y-mS[c+3])*rS[c+3],0.f));
            u.z = pack_h2(fmaxf((f2.x-mS[c+4])*rS[c+4],0.f), fmaxf((f2.y-mS[c+5])*rS[c+5],0.f));
            u.w = pack_h2(fmaxf((f3.x-mS[c+6])*rS[c+6],0.f), fmaxf((f3.y-mS[c+7])*rS[c+7],0.f));
            *(uint4*)&xH[s*36 + q*4] = u;
        }
        __syncthreads();
        if (tile+1 < XZ_TILES) {
            size_t nb = (base0 + (size_t)(tile+1)*128)*8;
#pragma unroll
            for (int j=0;j<4;j++) pf[j] = sv[nb + tid*4 + j];
        }
        float acc[2][4][4];
#pragma unroll
        for (int m=0;m<2;m++)
#pragma unroll
        for (int n=0;n<4;n++)
#pragma unroll
        for (int c=0;c<4;c++) acc[m][n][c]=0.f;
#pragma unroll
        for (int kk=0; kk<4; kk++) {
            int k0 = kk*8;
            unsigned a[2][4];
#pragma unroll
            for (int m=0;m<2;m++) {
                int r0 = (sOffW + m*16 + g)*36 + k0 + t4;
                a[m][0]=xH[r0]; a[m][1]=xH[r0+8*36];
                a[m][2]=xH[r0+4]; a[m][3]=xH[r0+8*36+4];
            }
#pragma unroll
            for (int m=0;m<2;m++)
#pragma unroll
            for (int n=0;n<4;n++) MMA_F16(acc[m][n], a[m], bR[kk][n]);
        }
#pragma unroll
        for (int m=0;m<2;m++)
#pragma unroll
        for (int n=0;n<4;n++) {
            stS[n*2  ] += acc[m][n][0] + acc[m][n][2];
            stS[n*2+1] += acc[m][n][1] + acc[m][n][3];
            stQ[n*2  ] = fmaf(acc[m][n][0],acc[m][n][0], fmaf(acc[m][n][2],acc[m][n][2], stQ[n*2  ]));
            stQ[n*2+1] = fmaf(acc[m][n][1],acc[m][n][1], fmaf(acc[m][n][3],acc[m][n][3], stQ[n*2+1]));
        }
        __syncthreads();
    }
#pragma unroll
    for (int n=0;n<4;n++)
#pragma unroll
    for (int p=0;p<2;p++) {
        int col = nOffW + n*8 + 2*t4 + p;
        atomicAdd(&ssS[col], stS[n*2+p]);
        atomicAdd(&sqS[col], stQ[n*2+p]);
    }
    __syncthreads();
    if (tid < 64) {
        atomicAdd(&d_stats[slot_z*256 + tid],      ssS[tid]);
        atomicAdd(&d_stats[slot_z*256 + 64 + tid], sqS[tid]);
    }
}

// ------- pool: recompute z in-kernel (MMA), softmax, weighted sum, mw GEMM ----
#define POOL_TILES 8
__global__ void pool_kernel(const __half* __restrict__ y1, const __half* __restrict__ y2,
                            float* __restrict__ gg1, float* __restrict__ gg2,
                            const float* __restrict__ sw1a, const float* __restrict__ sw2a,
                            const float* __restrict__ mwa,
                            const float* __restrict__ sw1b, const float* __restrict__ sw2b,
                            const float* __restrict__ mwb) {
    int br = blockIdx.y;
    const __half* src = br ? y2 : y1;
    float*        gg  = br ? gg2 : gg1;
    const float*  sw1 = br ? sw1b : sw1a;
    const float*  sw2 = br ? sw2b : sw2a;
    const float*  mw  = br ? mwb  : mwa;
    int slot_y = br ? 3 : 0, slot_z = br ? 4 : 1, slot_g = br ? 5 : 2;
    __shared__ unsigned xS[128*36];     // x fp16 pairs
    __shared__ unsigned wS[64*36];      // sw1 fp16 pairs
    __shared__ float2 mw2[64*32];       // (mw[l][c], mw[l+32][c])
    __shared__ float mS[64], rS[64], mzS[64], rzS[64], sw2S[64];
    __shared__ float zsc[128];
    __shared__ float pkS[128];
    __shared__ float featS[8][Hh];
    __shared__ float ss[64], sq[64];
    int tid = threadIdx.x;              // 256
    for (int i=tid; i<64*32; i+=256) {
        int n = i>>5, k2 = i&31;
        wS[n*36+k2] = pack_h2(sw1[n*64+2*k2], sw1[n*64+2*k2+1]);
    }
    for (int i=tid; i<64*32; i+=256) {
        int c = i>>5, l = i&31;
        mw2[i] = make_float2(mw[l*Hh+c], mw[(l+32)*Hh+c]);
    }
    if (tid < 64) {
        float m = d_stats[slot_y*256+tid]*INV_S;
        float v = d_stats[slot_y*256+64+tid]*INV_S - m*m;
        mS[tid]=m; rS[tid]=rsqrtf(v+1e-5f);
        m = d_stats[slot_z*256+tid]*INV_S;
        v = d_stats[slot_z*256+64+tid]*INV_S - m*m;
        mzS[tid]=m; rzS[tid]=rsqrtf(v+1e-5f);
        sw2S[tid]=sw2[tid]; ss[tid]=0.f; sq[tid]=0.f;
    }
    int w = tid>>5, lane = tid&31, g = lane>>2, t4 = lane&3;
    int wM = w&3, wN = w>>2;
    int sOffW = wM*32, nOffW = wN*32;
    float sSa=0.f, sQa=0.f, sSb=0.f, sQb=0.f;
    const uint4* sv = (const uint4*)src;
    size_t base0 = (size_t)blockIdx.x*POOL_TILES*128;
    uint4 pf[4];
#pragma unroll
    for (int j=0;j<4;j++) pf[j] = sv[base0*8 + tid*4 + j];
    __syncthreads();
    unsigned bR[4][4][2];
#pragma unroll
    for (int kk=0; kk<4; kk++)
#pragma unroll
    for (int n=0;n<4;n++) {
        int rb = (nOffW + n*8 + g)*36 + kk*8 + t4;
        bR[kk][n][0]=wS[rb]; bR[kk][n][1]=wS[rb+4];
    }
    for (int tile=0; tile<POOL_TILES; tile++) {
        // A: stage x tile + zero score accum
        if (tid < 128) zsc[tid] = 0.f;
#pragma unroll
        for (int j=0;j<4;j++) {
            int e = tid*4 + j;
            int s = e>>3, q = e&7, c = q*8;
            __half2* hp = (__half2*)&pf[j];
            float2 f0 = __half22float2(hp[0]);
            float2 f1 = __half22float2(hp[1]);
            float2 f2 = __half22float2(hp[2]);
            float2 f3 = __half22float2(hp[3]);
            uint4 u;
            u.x = pack_h2(fmaxf((f0.x-mS[c  ])*rS[c  ],0.f), fmaxf((f0.y-mS[c+1])*rS[c+1],0.f));
            u.y = pack_h2(fmaxf((f1.x-mS[c+2])*rS[c+2],0.f), fmaxf((f1.y-mS[c+3])*rS[c+3],0.f));
            u.z = pack_h2(fmaxf((f2.x-mS[c+4])*rS[c+4],0.f), fmaxf((f2.y-mS[c+5])*rS[c+5],0.f));
            u.w = pack_h2(fmaxf((f3.x-mS[c+6])*rS[c+6],0.f), fmaxf((f3.y-mS[c+7])*rS[c+7],0.f));
            *(uint4*)&xS[s*36 + q*4] = u;
        }
        __syncthreads();
        if (tile+1 < POOL_TILES) {
            size_t nb = (base0 + (size_t)(tile+1)*128)*8;
#pragma unroll
            for (int j=0;j<4;j++) pf[j] = sv[nb + tid*4 + j];
        }
        // B: z = x @ sw1^T (fragments)
        float acc[2][4][4];
#pragma unroll
        for (int m=0;m<2;m++)
#pragma unroll
        for (int n=0;n<4;n++)
#pragma unroll
        for (int c=0;c<4;c++) acc[m][n][c]=0.f;
#pragma unroll
        for (int kk=0; kk<4; kk++) {
            int k0 = kk*8;
            unsigned a[2][4];
#pragma unroll
            for (int m=0;m<2;m++) {
                int r0 = (sOffW + m*16 + g)*36 + k0 + t4;
                a[m][0]=xS[r0]; a[m][1]=xS[r0+8*36];
                a[m][2]=xS[r0+4]; a[m][3]=xS[r0+8*36+4];
            }
#pragma unroll
            for (int m=0;m<2;m++)
#pragma unroll
            for (int n=0;n<4;n++) MMA_F16(acc[m][n], a[m], bR[kk][n]);
        }
        // C: score partials from fragments
#pragma unroll
        for (int m=0;m<2;m++) {
            float sp0 = 0.f, sp1 = 0.f;
#pragma unroll
            for (int n=0;n<4;n++) {
                int c = nOffW + n*8 + 2*t4;
                sp0 += fmaxf((acc[m][n][0]-mzS[c  ])*rzS[c  ],0.f)*sw2S[c  ]
                     + fmaxf((acc[m][n][1]-mzS[c+1])*rzS[c+1],0.f)*sw2S[c+1];
                sp1 += fmaxf((acc[m][n][2]-mzS[c  ])*rzS[c  ],0.f)*sw2S[c  ]
                     + fmaxf((acc[m][n][3]-mzS[c+1])*rzS[c+1],0.f)*sw2S[c+1];
            }
            sp0 += __shfl_xor_sync(0xffffffffu, sp0, 1);
            sp0 += __shfl_xor_sync(0xffffffffu, sp0, 2);
            sp1 += __shfl_xor_sync(0xffffffffu, sp1, 1);
            sp1 += __shfl_xor_sync(0xffffffffu, sp1, 2);
            if (t4 == 0) {
                atomicAdd(&zsc[sOffW + m*16 + g],     sp0);
                atomicAdd(&zsc[sOffW + m*16 + 8 + g], sp1);
            }
        }
        __syncthreads();
        // D: softmax over k (16-lane groups; tid<128)
        if (tid < 128) {
            float val = zsc[tid];
            float mx = val;
#pragma unroll
            for (int msk=1; msk<16; msk<<=1) mx = fmaxf(mx, __shfl_xor_sync(0xffffffffu, mx, msk));
            float e = __expf(val - mx);
            float den = e;
#pragma unroll
            for (int msk=1; msk<16; msk<<=1) den += __shfl_xor_sync(0xffffffffu, den, msk);
            pkS[tid] = e / den;
        }
        __syncthreads();
        // E: weighted sum over k -> feat
        {
            int p = tid>>5, cp = tid&31;
            float fa=0.f, fb=0.f;
#pragma unroll
            for (int k=0;k<16;k++) {
                float pk = pkS[p*16+k];
                __half2 h = *(__half2*)&xS[(p*16+k)*36 + cp];
                float2 f = __half22float2(h);
                fa = fmaf(f.x, pk, fa);
                fb = fmaf(f.y, pk, fb);
            }
            featS[p][2*cp]   = fa;
            featS[p][2*cp+1] = fb;
        }
        __syncthreads();
        // F: g = feat @ mw^T + stats
        {
            int p = tid>>5, l = tid&31;
            float ga=0.f, gb=0.f;
#pragma unroll 16
            for (int c=0;c<Hh;c++) {
                float f = featS[p][c];
                float2 wv = mw2[c*32 + l];
                ga = fmaf(f, wv.x, ga);
                gb = fmaf(f, wv.y, gb);
            }
            int pt = blockIdx.x*POOL_TILES*8 + tile*8 + p;
            gg[(size_t)pt*Hh + l]      = ga;
            gg[(size_t)pt*Hh + 32 + l] = gb;
            sSa += ga; sQa = fmaf(ga,ga,sQa);
            sSb += gb; sQb = fmaf(gb,gb,sQb);
        }
        __syncthreads();
    }
    atomicAdd(&ss[lane], sSa);      atomicAdd(&sq[lane], sQa);
    atomicAdd(&ss[32+lane], sSb);   atomicAdd(&sq[32+lane], sQb);
    __syncthreads();
    if (tid < 64) {
        atomicAdd(&d_stats[slot_g*256 + tid],      ss[tid]);
        atomicAdd(&d_stats[slot_g*256 + 64 + tid], sq[tid]);
    }
}

// ------- DRB matmul (split-A tf32) ---------------------------------------------
__global__ void drb_mma_kernel(const float* __restrict__ s1, const float* __restrict__ s2,
                               float* __restrict__ dst, const float* __restrict__ wmat,
                               int mode) {
    extern __shared__ unsigned sh[];
    unsigned* xHi = sh;                  // [128][132]
    unsigned* xLo = sh + 128*132;
    unsigned* wS  = sh + 2*128*132;      // [128][132]
    __shared__ float mS[OUTC], rS[OUTC], ssS[OUTC], sqS[OUTC];
    int slot_out = (mode==0) ? 6 : 7;
    int tid = threadIdx.x;               // 512
    for (int i=tid; i<OUTC*OUTC; i+=512) {
        int n = i>>7, k = i&127;
        wS[n*132+k] = tf32r(wmat[i]);
    }
    if (tid < 128) {
        ssS[tid]=0.f; sqS[tid]=0.f;
        float m, v;
        if (mode == 0) {
            int slot = (tid < 64) ? 2 : 5;
            int ch = tid & 63;
            m = d_stats[slot*256+ch]*INV_P;
            v = d_stats[slot*256+64+ch]*INV_P - m*m;
        } else {
            m = d_stats[6*256+tid]*INV_P;
            v = d_stats[6*256+128+tid]*INV_P - m*m;
        }
        mS[tid]=m; rS[tid]=rsqrtf(v+1e-5f);
    }
    int w = tid>>5, lane = tid&31, g = lane>>2, t4 = lane&3;
    int wM = w&3, wN = w>>2;
    int sOffW = wM*32, nOffW = wN*32;
    int base = blockIdx.x*128;
    __syncthreads();
    for (int i=tid; i<128*32; i+=512) {
        int s = i>>5, q = i&31, c = q*4;
        float4 v;
        if (mode == 0) {
            if (c < 64) v = ((const float4*)(s1 + (size_t)(base+s)*Hh))[q];
            else        v = ((const float4*)(s2 + (size_t)(base+s)*Hh))[q-16];
        } else {
            v = ((const float4*)(s1 + (size_t)(base+s)*OUTC))[q];
        }
        v.x = fmaxf((v.x-mS[c  ])*rS[c  ], 0.f);
        v.y = fmaxf((v.y-mS[c+1])*rS[c+1], 0.f);
        v.z = fmaxf((v.z-mS[c+2])*rS[c+2], 0.f);
        v.w = fmaxf((v.w-mS[c+3])*rS[c+3], 0.f);
        if (mode == 0) *(float4*)&g_agg[(size_t)(base+s)*OUTC + c] = v;
        float vv[4] = {v.x, v.y, v.z, v.w};
#pragma unroll
        for (int j=0;j<4;j++) {
            unsigned hi = tf32r(vv[j]);
            xHi[s*132 + c + j] = hi;
            xLo[s*132 + c + j] = tf32r(vv[j] - __uint_as_float(hi));
        }
    }
    __syncthreads();
    float acc[2][4][4];
#pragma unroll
    for (int m=0;m<2;m++)
#pragma unroll
    for (int n=0;n<4;n++)
#pragma unroll
    for (int c=0;c<4;c++) acc[m][n][c]=0.f;
#pragma unroll
    for (int kk=0; kk<16; kk++) {
        int k0 = kk*8;
        unsigned aH[2][4], aL[2][4], b[4][2];
#pragma unroll
        for (int m=0;m<2;m++) {
            int r0 = (sOffW + m*16 + g)*132 + k0 + t4;
            aH[m][0]=xHi[r0]; aH[m][1]=xHi[r0+8*132];
            aH[m][2]=xHi[r0+4]; aH[m][3]=xHi[r0+8*132+4];
            aL[m][0]=xLo[r0]; aL[m][1]=xLo[r0+8*132];
            aL[m][2]=xLo[r0+4]; aL[m][3]=xLo[r0+8*132+4];
        }
#pragma unroll
        for (int n=0;n<4;n++) {
            int rb = (nOffW + n*8 + g)*132 + k0 + t4;
            b[n][0]=wS[rb]; b[n][1]=wS[rb+4];
        }
#pragma unroll
        for (int m=0;m<2;m++)
#pragma unroll
        for (int n=0;n<4;n++) {
            MMA_TF32(acc[m][n], aL[m], b[n]);
            MMA_TF32(acc[m][n], aH[m], b[n]);
        }
    }
    float stS[8]={0,0,0,0,0,0,0,0}, stQ[8]={0,0,0,0,0,0,0,0};
#pragma unroll
    for (int m=0;m<2;m++)
#pragma unroll
    for (int n=0;n<4;n++) {
        int row = base + sOffW + m*16 + g;
        int col = nOffW + n*8 + 2*t4;
        *(float2*)&dst[(size_t)row*OUTC + col]     = make_float2(acc[m][n][0], acc[m][n][1]);
        *(float2*)&dst[(size_t)(row+8)*OUTC + col] = make_float2(acc[m][n][2], acc[m][n][3]);
        stS[n*2  ] += acc[m][n][0] + acc[m][n][2];
        stS[n*2+1] += acc[m][n][1] + acc[m][n][3];
        stQ[n*2  ] = fmaf(acc[m][n][0],acc[m][n][0], fmaf(acc[m][n][2],acc[m][n][2], stQ[n*2  ]));
        stQ[n*2+1] = fmaf(acc[m][n][1],acc[m][n][1], fmaf(acc[m][n][3],acc[m][n][3], stQ[n*2+1]));
    }
#pragma unroll
    for (int n=0;n<4;n++)
#pragma unroll
    for (int p=0;p<2;p++) {
        int col = nOffW + n*8 + 2*t4 + p;
        atomicAdd(&ssS[col], stS[n*2+p]);
        atomicAdd(&sqS[col], stQ[n*2+p]);
    }
    __syncthreads();
    if (tid < 128) {
        atomicAdd(&d_stats[slot_out*256 + tid],       ssS[tid]);
        atomicAdd(&d_stats[slot_out*256 + 128 + tid], sqS[tid]);
    }
}

// ------- out = relu(bn(h2) + agg) ---------------------------------------------
__global__ void final_kernel(float* __restrict__ out) {
    __shared__ float mS[128], rS[128];
    int tid = threadIdx.x;
    if (tid < 128) {
        float m = d_stats[7*256+tid]*INV_P;
        float v = d_stats[7*256+128+tid]*INV_P - m*m;
        mS[tid]=m; rS[tid]=rsqrtf(v+1e-5f);
    }
    __syncthreads();
    for (int t = blockIdx.x*256 + tid; t < P_TOT*32; t += gridDim.x*256) {
        int q = t & 31, c = q*4;
        float4 h = ((const float4*)g_h2)[t];
        float4 a = ((const float4*)g_agg)[t];
        float4 o;
        o.x = fmaxf((h.x-mS[c  ])*rS[c  ] + a.x, 0.f);
        o.y = fmaxf((h.y-mS[c+1])*rS[c+1] + a.y, 0.f);
        o.z = fmaxf((h.z-mS[c+2])*rS[c+2] + a.z, 0.f);
        o.w = fmaxf((h.w-mS[c+3])*rS[c+3] + a.w, 0.f);
        ((float4*)out)[t] = o;
    }
}

// ------------------------------ launch ----------------------------------------
extern "C" void kernel_launch(void* const* d_in, const int* in_sizes, int n_in,
                              void* d_out, int out_size) {
    const float* xyz     = (const float*)d_in[0];
    const float* feat    = (const float*)d_in[1];
    const float* w_lse1  = (const float*)d_in[2];
    const float* w_lse2  = (const float*)d_in[3];
    const float* ap1_sw1 = (const float*)d_in[4];
    const float* ap1_sw2 = (const float*)d_in[5];
    const float* ap1_mw  = (const float*)d_in[7];
    const float* ap2_sw1 = (const float*)d_in[8];
    const float* ap2_sw2 = (const float*)d_in[9];
    const float* ap2_mw  = (const float*)d_in[11];
    const float* drb_w1  = (const float*)d_in[12];
    const float* drb_w2  = (const float*)d_in[13];
    float* out = (float*)d_out;

    size_t drb_smem = (size_t)(3*128*132) * 4;            // 198 KB
    cudaFuncSetAttribute(drb_mma_kernel, cudaFuncAttributeMaxDynamicSharedMemorySize, (int)drb_smem);

    __half *py1, *py2;
    float *pg1, *pg2, *ph1, *ph2;
    cudaGetSymbolAddress((void**)&py1, g_y1);
    cudaGetSymbolAddress((void**)&py2, g_y2);
    cudaGetSymbolAddress((void**)&pg1, g_g1);
    cudaGetSymbolAddress((void**)&pg2, g_g2);
    cudaGetSymbolAddress((void**)&ph1, g_h1);
    cudaGetSymbolAddress((void**)&ph2, g_h2);

    zero_stats_kernel<<<8,256>>>();
    knn_kernel<<<dim3(Nn/KNN_T, Bz), KNN_T>>>(xyz);
    lse_mma_kernel<<<512,256>>>(xyz, feat, w_lse1, w_lse2, py1, py2);
    zstats_kernel<<<dim3(512,2),256>>>(py1, py2, ap1_sw1, ap2_sw1);
    pool_kernel<<<dim3(512,2),256>>>(py1, py2, pg1, pg2,
                                     ap1_sw1, ap1_sw2, ap1_mw,
                                     ap2_sw1, ap2_sw2, ap2_mw);
    drb_mma_kernel<<<256,512,drb_smem>>>(pg1, pg2, ph1, drb_w1, 0);
    drb_mma_kernel<<<256,512,drb_smem>>>(ph1, ph1, ph2, drb_w2, 1);
    final_kernel<<<512,256>>>(out);
}

// round 12
// speedup vs baseline: 1.0437x; 1.0437x over previous
#include <cuda_runtime.h>
#include <cuda_fp16.h>
#include <math.h>

#define Bz   4
#define Nn   8192
#define Cc   32
#define Kk   16
#define Hh   64
#define OUTC 128
#define CE   36
#define S_TOT (Bz*Nn*Kk)        // 524288
#define P_TOT (Bz*Nn)           // 32768
#define INV_S (1.f/524288.f)
#define INV_P (1.f/32768.f)

// ---------------- scratch -----------------------------------------------------
__device__ __half g_y1 [S_TOT*Hh];
__device__ __half g_y2 [S_TOT*Hh];
__device__ __half g_z1 [S_TOT*Hh];
__device__ __half g_z2 [S_TOT*Hh];
__device__ float  g_g1 [P_TOT*Hh];
__device__ float  g_g2 [P_TOT*Hh];
__device__ float  g_agg[P_TOT*OUTC];
__device__ float  g_h1 [P_TOT*OUTC];
__device__ float  g_h2 [P_TOT*OUTC];
__device__ int    g_idx[S_TOT];
__device__ float  d_stats[8*256];

__device__ __forceinline__ unsigned tf32r(float f) {
    unsigned r; asm("cvt.rna.tf32.f32 %0, %1;" : "=r"(r) : "f"(f)); return r;
}
#define MMA_TF32(d, a, b) asm volatile( \
    "mma.sync.aligned.m16n8k8.row.col.f32.tf32.tf32.f32 " \
    "{%0,%1,%2,%3}, {%4,%5,%6,%7}, {%8,%9}, {%0,%1,%2,%3};" \
    : "+f"(d[0]),"+f"(d[1]),"+f"(d[2]),"+f"(d[3]) \
    : "r"(a[0]),"r"(a[1]),"r"(a[2]),"r"(a[3]), "r"(b[0]),"r"(b[1]))
#define MMA_F16(d, a, b) asm volatile( \
    "mma.sync.aligned.m16n8k16.row.col.f32.f16.f16.f32 " \
    "{%0,%1,%2,%3}, {%4,%5,%6,%7}, {%8,%9}, {%0,%1,%2,%3};" \
    : "+f"(d[0]),"+f"(d[1]),"+f"(d[2]),"+f"(d[3]) \
    : "r"(a[0]),"r"(a[1]),"r"(a[2]),"r"(a[3]), "r"(b[0]),"r"(b[1]))

__device__ __forceinline__ unsigned pack_h2(float a, float b) {
    __half2 h = __floats2half2_rn(a, b);
    return *(unsigned*)&h;
}
__device__ __forceinline__ void split_h2(float a, float b, unsigned &hi, unsigned &lo) {
    __half ha = __float2half_rn(a), hb = __float2half_rn(b);
    float la = a - __half2float(ha), lb = b - __half2float(hb);
    __half2 h = __halves2half2(ha, hb);
    __half2 l = __floats2half2_rn(la, lb);
    hi = *(unsigned*)&h; lo = *(unsigned*)&l;
}

__global__ void zero_stats_kernel(int off) {
    int t = off*1024 + blockIdx.x*256 + threadIdx.x;
    if (t < 8*256) d_stats[t] = 0.f;
}

// ---------------- KNN ---------------------------------------------------------
#define KNN_T    128
#define KNN_TILE 1024
__global__ void knn_kernel(const float* __restrict__ xyz) {
    int b = blockIdx.y;
    int n = blockIdx.x*KNN_T + threadIdx.x;
    const float* xb = xyz + b*Nn*3;
    float qx = xb[n*3+0], qy = xb[n*3+1], qz = xb[n*3+2];
    float m2x = -2.f*qx, m2y = -2.f*qy, m2z = -2.f*qz;
    float bd[16]; int bi[16];
#pragma unroll
    for (int t=0;t<16;t++){ bd[t]=3.4e38f; bi[t]=0; }
    __shared__ float4 sp[KNN_TILE];
    for (int tile=0; tile<Nn; tile+=KNN_TILE) {
        __syncthreads();
        for (int t=threadIdx.x; t<KNN_TILE; t+=KNN_T) {
            int j = tile + t;
            float x = xb[j*3+0], y = xb[j*3+1], z = xb[j*3+2];
            float w = x*x; w = fmaf(y,y,w); w = fmaf(z,z,w);
            sp[t] = make_float4(x, y, z, w);
        }
        __syncthreads();
#pragma unroll 8
        for (int jj=0; jj<KNN_TILE; jj++) {
            float4 c = sp[jj];
            float d = fmaf(c.x, m2x, fmaf(c.y, m2y, fmaf(c.z, m2z, c.w)));
            if (d < bd[15]) {
                bd[15]=d; bi[15]=tile+jj;
#pragma unroll
                for (int t=15;t>0;t--) {
                    if (bd[t] < bd[t-1]) {
                        float td=bd[t]; bd[t]=bd[t-1]; bd[t-1]=td;
                        int   ti=bi[t]; bi[t]=bi[t-1]; bi[t-1]=ti;
                    }
                }
            }
        }
    }
    int base = (b*Nn + n)*Kk;
#pragma unroll
    for (int t=0;t<16;t++) g_idx[base+t] = bi[t];
}

// ---------------- LSE (3xFP16 split, pipelined gather) ------------------------
#define LSE_TILES 16
__global__ void lse_mma_kernel(const float* __restrict__ xyz, const float* __restrict__ feat,
                               const float* __restrict__ w1, const float* __restrict__ w2,
                               __half* __restrict__ y1, __half* __restrict__ y2) {
    __shared__ unsigned encH[64*28], encL[64*28];
    __shared__ unsigned wH[128*28], wL[128*28];
    __shared__ float ssS[128], sqS[128];
    int tid = threadIdx.x;              // 256
    for (int i=tid; i<64*28;  i+=256) { encH[i]=0u; encL[i]=0u; }
    for (int i=tid; i<128*28; i+=256) { wH[i]=0u; wL[i]=0u; }
    if (tid < 128) { ssS[tid]=0.f; sqS[tid]=0.f; }
    __syncthreads();
    for (int i=tid; i<128*18; i+=256) {
        int n = i/18, k2 = i - n*18;
        const float* wsrc = (n < 64) ? (w1 + n*CE) : (w2 + (n-64)*CE);
        unsigned hi, lo;
        split_h2(wsrc[2*k2], wsrc[2*k2+1], hi, lo);
        wH[n*28+k2] = hi; wL[n*28+k2] = lo;
    }
    int w = tid>>5, lane = tid&31, g = lane>>2, t4 = lane&3;
    int wM = w&1, wN = w>>1;
    int sOffW = wM*32, nOffW = wN*32;
    int sl = tid>>2, gq = tid&3;
    float stS[8]={0,0,0,0,0,0,0,0}, stQ[8]={0,0,0,0,0,0,0,0};
    float4 pv0, pv1;
    float aj0=0,aj1=0,aj2=0, an0=0,an1=0,an2=0;
#define LSE_LOAD(T) { \
    int s = (blockIdx.x*LSE_TILES + (T))*64 + sl; \
    int bb = s >> 17; \
    int nn2 = (s >> 4) & (Nn-1); \
    int j = g_idx[s]; \
    const float4* fp = (const float4*)(feat + (size_t)(bb*Nn + j)*Cc + gq*8); \
    pv0 = fp[0]; pv1 = fp[1]; \
    if (gq == 0) { \
        const float* pj = xyz + (size_t)(bb*Nn + j)*3; \
        const float* pn = xyz + (size_t)(bb*Nn + nn2)*3; \
        aj0=pj[0]; aj1=pj[1]; aj2=pj[2]; an0=pn[0]; an1=pn[1]; an2=pn[2]; \
    } }
    LSE_LOAD(0);
    __syncthreads();
    for (int tile=0; tile<LSE_TILES; tile++) {
        int base = (blockIdx.x*LSE_TILES + tile)*64;
        {
            int h0 = sl*28 + 2 + gq*4;
            unsigned hi, lo;
            split_h2(pv0.x, pv0.y, hi, lo); encH[h0  ]=hi; encL[h0  ]=lo;
            split_h2(pv0.z, pv0.w, hi, lo); encH[h0+1]=hi; encL[h0+1]=lo;
            split_h2(pv1.x, pv1.y, hi, lo); encH[h0+2]=hi; encL[h0+2]=lo;
            split_h2(pv1.z, pv1.w, hi, lo); encH[h0+3]=hi; encL[h0+3]=lo;
            if (gq == 0) {
                float dx=aj0-an0, dy=aj1-an1, dz=aj2-an2;
                float dd = dx*dx; dd=fmaf(dy,dy,dd); dd=fmaf(dz,dz,dd);
                float ds = sqrtf(fmaxf(dd,1e-12f));
                split_h2(dx, dy, hi, lo); encH[sl*28  ]=hi; encL[sl*28  ]=lo;
                split_h2(dz, ds, hi, lo); encH[sl*28+1]=hi; encL[sl*28+1]=lo;
            }
        }
        __syncthreads();
        if (tile+1 < LSE_TILES) LSE_LOAD(tile+1);
        float acc[2][4][4];
#pragma unroll
        for (int m=0;m<2;m++)
#pragma unroll
        for (int n=0;n<4;n++)
#pragma unroll
        for (int c=0;c<4;c++) acc[m][n][c]=0.f;
#pragma unroll
        for (int kk=0; kk<3; kk++) {
            int k0 = kk*8;
            unsigned aH[2][4], aL[2][4], bH[4][2], bL[4][2];
#pragma unroll
            for (int m=0;m<2;m++) {
                int r0 = (sOffW + m*16 + g)*28 + k0 + t4;
                aH[m][0]=encH[r0]; aH[m][1]=encH[r0+8*28];
                aH[m][2]=encH[r0+4]; aH[m][3]=encH[r0+8*28+4];
                aL[m][0]=encL[r0]; aL[m][1]=encL[r0+8*28];
                aL[m][2]=encL[r0+4]; aL[m][3]=encL[r0+8*28+4];
            }
#pragma unroll
            for (int n=0;n<4;n++) {
                int rb = (nOffW + n*8 + g)*28 + k0 + t4;
                bH[n][0]=wH[rb]; bH[n][1]=wH[rb+4];
                bL[n][0]=wL[rb]; bL[n][1]=wL[rb+4];
            }
#pragma unroll
            for (int m=0;m<2;m++)
#pragma unroll
            for (int n=0;n<4;n++) {
                MMA_F16(acc[m][n], aL[m], bH[n]);
                MMA_F16(acc[m][n], aH[m], bL[n]);
                MMA_F16(acc[m][n], aH[m], bH[n]);
            }
        }
#pragma unroll
        for (int m=0;m<2;m++)
#pragma unroll
        for (int n=0;n<4;n++) {
            int row = base + sOffW + m*16 + g;
            int col = nOffW + n*8 + 2*t4;
            __half* dst = (col < 64) ? y1 : y2;
            int cc = col & 63;
            __half2 h0 = __floats2half2_rn(acc[m][n][0], acc[m][n][1]);
            __half2 h1 = __floats2half2_rn(acc[m][n][2], acc[m][n][3]);
            *(__half2*)&dst[(size_t)row*Hh + cc]     = h0;
            *(__half2*)&dst[(size_t)(row+8)*Hh + cc] = h1;
            stS[n*2  ] += acc[m][n][0] + acc[m][n][2];
            stS[n*2+1] += acc[m][n][1] + acc[m][n][3];
            stQ[n*2  ] = fmaf(acc[m][n][0],acc[m][n][0], fmaf(acc[m][n][2],acc[m][n][2], stQ[n*2  ]));
            stQ[n*2+1] = fmaf(acc[m][n][1],acc[m][n][1], fmaf(acc[m][n][3],acc[m][n][3], stQ[n*2+1]));
        }
        __syncthreads();
    }
#pragma unroll
    for (int n=0;n<4;n++)
#pragma unroll
    for (int p=0;p<2;p++) {
        int col = nOffW + n*8 + 2*t4 + p;
        atomicAdd(&ssS[col], stS[n*2+p]);
        atomicAdd(&sqS[col], stQ[n*2+p]);
    }
    __syncthreads();
    if (tid < 128) {
        int slot = (tid < 64) ? 0 : 3;
        int ch = tid & 63;
        atomicAdd(&d_stats[slot*256 + ch],      ssS[tid]);
        atomicAdd(&d_stats[slot*256 + 64 + ch], sqS[tid]);
    }
}

// ------- xz (fp16 MMA, 64-row tiles, 3 blocks/SM, reg prefetch) ----------------
#define XZ_TILES 16
__global__ __launch_bounds__(256, 3)
void xz_mma_kernel(const __half* __restrict__ y1, const __half* __restrict__ y2,
                   __half* __restrict__ z1, __half* __restrict__ z2,
                   const float* __restrict__ w1b, const float* __restrict__ w2b) {
    int br = blockIdx.y;
    const __half* src = br ? y2 : y1;
    __half*       dst = br ? z2 : z1;
    const float*  sw1 = br ? w2b : w1b;
    int slot_y = br ? 3 : 0, slot_z = br ? 4 : 1;
    __shared__ unsigned xH[64*36];
    __shared__ unsigned wHs[64*36];
    __shared__ float mS[64], rS[64], ssS[64], sqS[64];
    int tid = threadIdx.x;              // 256
    for (int i=tid; i<64*32; i+=256) {
        int n = i>>5, k2 = i&31;
        wHs[n*36+k2] = pack_h2(sw1[n*64+2*k2], sw1[n*64+2*k2+1]);
    }
    if (tid < 64) {
        float m = d_stats[slot_y*256+tid]*INV_S;
        float v = d_stats[slot_y*256+64+tid]*INV_S - m*m;
        mS[tid]=m; rS[tid]=rsqrtf(v+1e-5f);
        ssS[tid]=0.f; sqS[tid]=0.f;
    }
    int w = tid>>5, lane = tid&31, g = lane>>2, t4 = lane&3;
    int wM = w&1, wN = w>>1;            // 2 M-warps x 4 N-warps
    int sOffW = wM*32, nOffW = wN*16;
    float stS[4]={0,0,0,0}, stQ[4]={0,0,0,0};
    const uint4* sv = (const uint4*)src;
    size_t base0 = (size_t)blockIdx.x*XZ_TILES*64;   // rows
    uint4 pf[2];
#pragma unroll
    for (int j=0;j<2;j++) pf[j] = sv[base0*8 + tid*2 + j];
    __syncthreads();
    // B fragments register-resident (16 regs)
    unsigned bR[4][2][2];
#pragma unroll
    for (int kk=0; kk<4; kk++)
#pragma unroll
    for (int n=0;n<2;n++) {
        int rb = (nOffW + n*8 + g)*36 + kk*8 + t4;
        bR[kk][n][0]=wHs[rb]; bR[kk][n][1]=wHs[rb+4];
    }
    for (int tile=0; tile<XZ_TILES; tile++) {
#pragma unroll
        for (int j=0;j<2;j++) {
            int e = tid*2 + j;
            int s = e>>3, q = e&7, c = q*8;
            __half2* hp = (__half2*)&pf[j];
            float2 f0 = __half22float2(hp[0]);
            float2 f1 = __half22float2(hp[1]);
            float2 f2 = __half22float2(hp[2]);
            float2 f3 = __half22float2(hp[3]);
            uint4 u;
            u.x = pack_h2(fmaxf((f0.x-mS[c  ])*rS[c  ],0.f), fmaxf((f0.y-mS[c+1])*rS[c+1],0.f));
            u.y = pack_h2(fmaxf((f1.x-mS[c+2])*rS[c+2],0.f), fmaxf((f1.y-mS[c+3])*rS[c+3],0.f));
            u.z = pack_h2(fmaxf((f2.x-mS[c+4])*rS[c+4],0.f), fmaxf((f2.y-mS[c+5])*rS[c+5],0.f));
            u.w = pack_h2(fmaxf((f3.x-mS[c+6])*rS[c+6],0.f), fmaxf((f3.y-mS[c+7])*rS[c+7],0.f));
            *(uint4*)&xH[s*36 + q*4] = u;
        }
        __syncthreads();
        if (tile+1 < XZ_TILES) {
            size_t nb = (base0 + (size_t)(tile+1)*64)*8;
#pragma unroll
            for (int j=0;j<2;j++) pf[j] = sv[nb + tid*2 + j];
        }
        int base = (int)(base0 + tile*64);
        float acc[2][2][4];
#pragma unroll
        for (int m=0;m<2;m++)
#pragma unroll
        for (int n=0;n<2;n++)
#pragma unroll
        for (int c=0;c<4;c++) acc[m][n][c]=0.f;
#pragma unroll
        for (int kk=0; kk<4; kk++) {
            int k0 = kk*8;
            unsigned a[2][4];
#pragma unroll
            for (int m=0;m<2;m++) {
                int r0 = (sOffW + m*16 + g)*36 + k0 + t4;
                a[m][0]=xH[r0]; a[m][1]=xH[r0+8*36];
                a[m][2]=xH[r0+4]; a[m][3]=xH[r0+8*36+4];
            }
#pragma unroll
            for (int m=0;m<2;m++)
#pragma unroll
            for (int n=0;n<2;n++) MMA_F16(acc[m][n], a[m], bR[kk][n]);
        }
#pragma unroll
        for (int m=0;m<2;m++)
#pragma unroll
        for (int n=0;n<2;n++) {
            int row = base + sOffW + m*16 + g;
            int col = nOffW + n*8 + 2*t4;
            __half2 h0 = __floats2half2_rn(acc[m][n][0], acc[m][n][1]);
            __half2 h1 = __floats2half2_rn(acc[m][n][2], acc[m][n][3]);
            *(__half2*)&dst[(size_t)row*Hh + col]     = h0;
            *(__half2*)&dst[(size_t)(row+8)*Hh + col] = h1;
            stS[n*2  ] += acc[m][n][0] + acc[m][n][2];
            stS[n*2+1] += acc[m][n][1] + acc[m][n][3];
            stQ[n*2  ] = fmaf(acc[m][n][0],acc[m][n][0], fmaf(acc[m][n][2],acc[m][n][2], stQ[n*2  ]));
            stQ[n*2+1] = fmaf(acc[m][n][1],acc[m][n][1], fmaf(acc[m][n][3],acc[m][n][3], stQ[n*2+1]));
        }
        __syncthreads();
    }
#pragma unroll
    for (int n=0;n<2;n++)
#pragma unroll
    for (int p=0;p<2;p++) {
        int col = nOffW + n*8 + 2*t4 + p;
        atomicAdd(&ssS[col], stS[n*2+p]);
        atomicAdd(&sqS[col], stQ[n*2+p]);
    }
    __syncthreads();
    if (tid < 64) {
        atomicAdd(&d_stats[slot_z*256 + tid],      ssS[tid]);
        atomicAdd(&d_stats[slot_z*256 + 64 + tid], sqS[tid]);
    }
}

// ------- attentive pool: warp-per-point ----------------------------------------
#define POOL_PW 8
__global__ void pool_kernel(const __half* __restrict__ x1, const __half* __restrict__ zz1,
                            float* __restrict__ gg1,
                            const float* __restrict__ sw2a, const float* __restrict__ mwa,
                            const __half* __restrict__ x2, const __half* __restrict__ zz2,
                            float* __restrict__ gg2,
                            const float* __restrict__ sw2b, const float* __restrict__ mwb) {
    int br = blockIdx.y;
    const __half* gx = br ? x2 : x1;
    const __half* gz = br ? zz2 : zz1;
    float*        gg = br ? gg2 : gg1;
    const float* sw2 = br ? sw2b : sw2a;
    const float* mw  = br ? mwb  : mwa;
    int slot_y = br ? 3 : 0, slot_z = br ? 4 : 1, slot_g = br ? 5 : 2;
    __shared__ float2 mw2[Hh*32];
    __shared__ float featS[8][Hh];
    __shared__ float myS[64], ryS[64], mzS[64], rzS[64], sw2S[64];
    __shared__ float ss[64], sq[64];
    int tid = threadIdx.x;              // 256
    for (int i=tid; i<Hh*32; i+=256) {
        int c=i>>5, l=i&31;
        mw2[i] = make_float2(mw[l*Hh+c], mw[(l+32)*Hh+c]);
    }
    if (tid < 64) {
        float m = d_stats[slot_y*256+tid]*INV_S;
        float v = d_stats[slot_y*256+64+tid]*INV_S - m*m;
        myS[tid]=m; ryS[tid]=rsqrtf(v+1e-5f);
        m = d_stats[slot_z*256+tid]*INV_S;
        v = d_stats[slot_z*256+64+tid]*INV_S - m*m;
        mzS[tid]=m; rzS[tid]=rsqrtf(v+1e-5f);
        sw2S[tid]=sw2[tid]; ss[tid]=0.f; sq[tid]=0.f;
    }
    __syncthreads();
    int w = tid>>5, lane = tid&31, kg = lane>>3, cg = lane&7;
    int c0 = cg*8;
    float sSa=0.f, sQa=0.f, sSb=0.f, sQb=0.f;
    int p0 = (blockIdx.x*8 + w)*POOL_PW;
    for (int it=0; it<POOL_PW; it++) {
        int p = p0 + it;
        const uint4* xp = (const uint4*)(gx + (size_t)p*Kk*Hh);
        const uint4* zp = (const uint4*)(gz + (size_t)p*Kk*Hh);
        float xv[4][8];
        float sp[4];
#pragma unroll
        for (int i=0;i<4;i++) {
            int row = kg*4 + i;
            uint4 ux = xp[row*8 + cg];
            uint4 uz = zp[row*8 + cg];
            __half2* hx = (__half2*)&ux;
            __half2* hz = (__half2*)&uz;
            float s = 0.f;
#pragma unroll
            for (int q=0;q<4;q++) {
                float2 fx = __half22float2(hx[q]);
                float2 fz = __half22float2(hz[q]);
                int c = c0 + 2*q;
                xv[i][2*q  ] = fmaxf((fx.x-myS[c  ])*ryS[c  ], 0.f);
                xv[i][2*q+1] = fmaxf((fx.y-myS[c+1])*ryS[c+1], 0.f);
                s += fmaxf((fz.x-mzS[c  ])*rzS[c  ],0.f)*sw2S[c  ];
                s += fmaxf((fz.y-mzS[c+1])*rzS[c+1],0.f)*sw2S[c+1];
            }
            sp[i] = s;
        }
#pragma unroll
        for (int i=0;i<4;i++) {
            sp[i] += __shfl_xor_sync(0xffffffffu, sp[i], 1);
            sp[i] += __shfl_xor_sync(0xffffffffu, sp[i], 2);
            sp[i] += __shfl_xor_sync(0xffffffffu, sp[i], 4);
        }
        float mx = fmaxf(fmaxf(sp[0],sp[1]), fmaxf(sp[2],sp[3]));
#pragma unroll
        for (int msk=1; msk<32; msk<<=1) mx = fmaxf(mx, __shfl_xor_sync(0xffffffffu, mx, msk));
        float e0=__expf(sp[0]-mx), e1=__expf(sp[1]-mx), e2=__expf(sp[2]-mx), e3=__expf(sp[3]-mx);
        float ls = e0+e1+e2+e3;
#pragma unroll
        for (int msk=1; msk<32; msk<<=1) ls += __shfl_xor_sync(0xffffffffu, ls, msk);
        float inv = 8.f/ls;
        float pk[4] = {e0*inv, e1*inv, e2*inv, e3*inv};
        float fpv[8];
#pragma unroll
        for (int j=0;j<8;j++) {
            float f = xv[0][j]*pk[0];
            f = fmaf(xv[1][j], pk[1], f);
            f = fmaf(xv[2][j], pk[2], f);
            f = fmaf(xv[3][j], pk[3], f);
            fpv[j] = f;
        }
#pragma unroll
        for (int j=0;j<8;j++) {
            fpv[j] += __shfl_xor_sync(0xffffffffu, fpv[j], 8);
            fpv[j] += __shfl_xor_sync(0xffffffffu, fpv[j], 16);
        }
        if (kg == 0) {
#pragma unroll
            for (int j=0;j<8;j++) featS[w][c0+j] = fpv[j];
        }
        __syncwarp();
        float ga=0.f, gb=0.f;
#pragma unroll 16
        for (int c=0;c<Hh;c++) {
            float f = featS[w][c];
            float2 wv = mw2[c*32 + lane];
            ga = fmaf(f, wv.x, ga);
            gb = fmaf(f, wv.y, gb);
        }
        gg[(size_t)p*Hh + lane]      = ga;
        gg[(size_t)p*Hh + 32 + lane] = gb;
        sSa += ga; sQa = fmaf(ga,ga,sQa);
        sSb += gb; sQb = fmaf(gb,gb,sQb);
        __syncwarp();
    }
    atomicAdd(&ss[lane], sSa);      atomicAdd(&sq[lane], sQa);
    atomicAdd(&ss[32+lane], sSb);   atomicAdd(&sq[32+lane], sQb);
    __syncthreads();
    if (tid < 64) {
        atomicAdd(&d_stats[slot_g*256 + tid],      ss[tid]);
        atomicAdd(&d_stats[slot_g*256 + 64 + tid], sq[tid]);
    }
}

// ------- DRB matmul (split-A tf32) ---------------------------------------------
__global__ void drb_mma_kernel(const float* __restrict__ s1, const float* __restrict__ s2,
                               float* __restrict__ dst, const float* __restrict__ wmat,
                               int mode) {
    extern __shared__ unsigned sh[];
    unsigned* xHi = sh;                  // [128][132]
    unsigned* xLo = sh + 128*132;
    unsigned* wS  = sh + 2*128*132;      // [128][132]
    __shared__ float mS[OUTC], rS[OUTC], ssS[OUTC], sqS[OUTC];
    int slot_out = (mode==0) ? 6 : 7;
    int tid = threadIdx.x;               // 512
    for (int i=tid; i<OUTC*OUTC; i+=512) {
        int n = i>>7, k = i&127;
        wS[n*132+k] = tf32r(wmat[i]);
    }
    if (tid < 128) {
        ssS[tid]=0.f; sqS[tid]=0.f;
        float m, v;
        if (mode == 0) {
            int slot = (tid < 64) ? 2 : 5;
            int ch = tid & 63;
            m = d_stats[slot*256+ch]*INV_P;
            v = d_stats[slot*256+64+ch]*INV_P - m*m;
        } else {
            m = d_stats[6*256+tid]*INV_P;
            v = d_stats[6*256+128+tid]*INV_P - m*m;
        }
        mS[tid]=m; rS[tid]=rsqrtf(v+1e-5f);
    }
    int w = tid>>5, lane = tid&31, g = lane>>2, t4 = lane&3;
    int wM = w&3, wN = w>>2;
    int sOffW = wM*32, nOffW = wN*32;
    int base = blockIdx.x*128;
    __syncthreads();
    for (int i=tid; i<128*32; i+=512) {
        int s = i>>5, q = i&31, c = q*4;
        float4 v;
        if (mode == 0) {
            if (c < 64) v = ((const float4*)(s1 + (size_t)(base+s)*Hh))[q];
            else        v = ((const float4*)(s2 + (size_t)(base+s)*Hh))[q-16];
        } else {
            v = ((const float4*)(s1 + (size_t)(base+s)*OUTC))[q];
        }
        v.x = fmaxf((v.x-mS[c  ])*rS[c  ], 0.f);
        v.y = fmaxf((v.y-mS[c+1])*rS[c+1], 0.f);
        v.z = fmaxf((v.z-mS[c+2])*rS[c+2], 0.f);
        v.w = fmaxf((v.w-mS[c+3])*rS[c+3], 0.f);
        if (mode == 0) *(float4*)&g_agg[(size_t)(base+s)*OUTC + c] = v;
        float vv[4] = {v.x, v.y, v.z, v.w};
#pragma unroll
        for (int j=0;j<4;j++) {
            unsigned hi = tf32r(vv[j]);
            xHi[s*132 + c + j] = hi;
            xLo[s*132 + c + j] = tf32r(vv[j] - __uint_as_float(hi));
        }
    }
    __syncthreads();
    float acc[2][4][4];
#pragma unroll
    for (int m=0;m<2;m++)
#pragma unroll
    for (int n=0;n<4;n++)
#pragma unroll
    for (int c=0;c<4;c++) acc[m][n][c]=0.f;
#pragma unroll
    for (int kk=0; kk<16; kk++) {
        int k0 = kk*8;
        unsigned aH[2][4], aL[2][4], b[4][2];
#pragma unroll
        for (int m=0;m<2;m++) {
            int r0 = (sOffW + m*16 + g)*132 + k0 + t4;
            aH[m][0]=xHi[r0]; aH[m][1]=xHi[r0+8*132];
            aH[m][2]=xHi[r0+4]; aH[m][3]=xHi[r0+8*132+4];
            aL[m][0]=xLo[r0]; aL[m][1]=xLo[r0+8*132];
            aL[m][2]=xLo[r0+4]; aL[m][3]=xLo[r0+8*132+4];
        }
#pragma unroll
        for (int n=0;n<4;n++) {
            int rb = (nOffW + n*8 + g)*132 + k0 + t4;
            b[n][0]=wS[rb]; b[n][1]=wS[rb+4];
        }
#pragma unroll
        for (int m=0;m<2;m++)
#pragma unroll
        for (int n=0;n<4;n++) {
            MMA_TF32(acc[m][n], aL[m], b[n]);
            MMA_TF32(acc[m][n], aH[m], b[n]);
        }
    }
    float stS[8]={0,0,0,0,0,0,0,0}, stQ[8]={0,0,0,0,0,0,0,0};
#pragma unroll
    for (int m=0;m<2;m++)
#pragma unroll
    for (int n=0;n<4;n++) {
        int row = base + sOffW + m*16 + g;
        int col = nOffW + n*8 + 2*t4;
        *(float2*)&dst[(size_t)row*OUTC + col]     = make_float2(acc[m][n][0], acc[m][n][1]);
        *(float2*)&dst[(size_t)(row+8)*OUTC + col] = make_float2(acc[m][n][2], acc[m][n][3]);
        stS[n*2  ] += acc[m][n][0] + acc[m][n][2];
        stS[n*2+1] += acc[m][n][1] + acc[m][n][3];
        stQ[n*2  ] = fmaf(acc[m][n][0],acc[m][n][0], fmaf(acc[m][n][2],acc[m][n][2], stQ[n*2  ]));
        stQ[n*2+1] = fmaf(acc[m][n][1],acc[m][n][1], fmaf(acc[m][n][3],acc[m][n][3], stQ[n*2+1]));
    }
#pragma unroll
    for (int n=0;n<4;n++)
#pragma unroll
    for (int p=0;p<2;p++) {
        int col = nOffW + n*8 + 2*t4 + p;
        atomicAdd(&ssS[col], stS[n*2+p]);
        atomicAdd(&sqS[col], stQ[n*2+p]);
    }
    __syncthreads();
    if (tid < 128) {
        atomicAdd(&d_stats[slot_out*256 + tid],       ssS[tid]);
        atomicAdd(&d_stats[slot_out*256 + 128 + tid], sqS[tid]);
    }
}

// ------- out = relu(bn(h2) + agg) ---------------------------------------------
__global__ void final_kernel(float* __restrict__ out) {
    __shared__ float mS[128], rS[128];
    int tid = threadIdx.x;
    if (tid < 128) {
        float m = d_stats[7*256+tid]*INV_P;
        float v = d_stats[7*256+128+tid]*INV_P - m*m;
        mS[tid]=m; rS[tid]=rsqrtf(v+1e-5f);
    }
    __syncthreads();
    for (int t = blockIdx.x*256 + tid; t < P_TOT*32; t += gridDim.x*256) {
        int q = t & 31, c = q*4;
        float4 h = ((const float4*)g_h2)[t];
        float4 a = ((const float4*)g_agg)[t];
        float4 o;
        o.x = fmaxf((h.x-mS[c  ])*rS[c  ] + a.x, 0.f);
        o.y = fmaxf((h.y-mS[c+1])*rS[c+1] + a.y, 0.f);
        o.z = fmaxf((h.z-mS[c+2])*rS[c+2] + a.z, 0.f);
        o.w = fmaxf((h.w-mS[c+3])*rS[c+3] + a.w, 0.f);
        ((float4*)out)[t] = o;
    }
}

// ------------------------------ launch ----------------------------------------
extern "C" void kernel_launch(void* const* d_in, const int* in_sizes, int n_in,
                              void* d_out, int out_size) {
    const float* xyz     = (const float*)d_in[0];
    const float* feat    = (const float*)d_in[1];
    const float* w_lse1  = (const float*)d_in[2];
    const float* w_lse2  = (const float*)d_in[3];
    const float* ap1_sw1 = (const float*)d_in[4];
    const float* ap1_sw2 = (const float*)d_in[5];
    const float* ap1_mw  = (const float*)d_in[7];
    const float* ap2_sw1 = (const float*)d_in[8];
    const float* ap2_sw2 = (const float*)d_in[9];
    const float* ap2_mw  = (const float*)d_in[11];
    const float* drb_w1  = (const float*)d_in[12];
    const float* drb_w2  = (const float*)d_in[13];
    float* out = (float*)d_out;

    size_t drb_smem = (size_t)(3*128*132) * 4;            // 198 KB
    cudaFuncSetAttribute(drb_mma_kernel, cudaFuncAttributeMaxDynamicSharedMemorySize, (int)drb_smem);

    __half *py1, *py2, *pz1, *pz2;
    float *pg1, *pg2, *ph1, *ph2;
    cudaGetSymbolAddress((void**)&py1, g_y1);
    cudaGetSymbolAddress((void**)&py2, g_y2);
    cudaGetSymbolAddress((void**)&pz1, g_z1);
    cudaGetSymbolAddress((void**)&pz2, g_z2);
    cudaGetSymbolAddress((void**)&pg1, g_g1);
    cudaGetSymbolAddress((void**)&pg2, g_g2);
    cudaGetSymbolAddress((void**)&ph1, g_h1);
    cudaGetSymbolAddress((void**)&ph2, g_h2);

    knn_kernel<<<dim3(Nn/KNN_T, Bz), KNN_T>>>(xyz);                     // 0
    zero_stats_kernel<<<4,256>>>(0);                                    // 1
    zero_stats_kernel<<<4,256>>>(1);                                    // 2
    lse_mma_kernel<<<512,256>>>(xyz, feat, w_lse1, w_lse2, py1, py2);   // 3 <- ncu
    xz_mma_kernel<<<dim3(512,2),256>>>(py1, py2, pz1, pz2, ap1_sw1, ap2_sw1); // 4
    pool_kernel<<<dim3(512,2),256>>>(py1, pz1, pg1, ap1_sw2, ap1_mw,
                                     py2, pz2, pg2, ap2_sw2, ap2_mw);   // 5
    drb_mma_kernel<<<256,512,drb_smem>>>(pg1, pg2, ph1, drb_w1, 0);     // 6
    drb_mma_kernel<<<256,512,drb_smem>>>(ph1, ph1, ph2, drb_w2, 1);     // 7
    final_kernel<<<512,256>>>(out);                                     // 8
}